// round 13
// baseline (speedup 1.0000x reference)
#include <cuda_runtime.h>
#include <cstddef>
#include <cstdint>

// ---------------- problem constants ----------------
#define BQ     4
#define DIMQ   512
#define LQ     4096
#define DSTATE 16
#define DINNER 1024
#define DTRANK 32
#define MQ     (BQ * LQ)            // 16384 rows (b,l)
#define NCHUNK 32
#define LCHUNK (LQ / NCHUNK)        // 128

// ---------------- scratch layout (floats) ----------------
#define OFF_XN    ((size_t)0)                                   // 16384 x 512 (tf32-rounded)
#define OFF_XZ    (OFF_XN    + (size_t)MQ * DIMQ)               // 16384 x 2048
#define OFF_U     (OFF_XZ    + (size_t)MQ * 2 * DINNER)         // 16384 x 1024
#define OFF_DBL   (OFF_U     + (size_t)MQ * DINNER)             // 16384 x 64
#define OFF_DELTA (OFF_DBL   + (size_t)MQ * 64)                 // 16384 x 1024
#define OFF_Y     (OFF_DELTA + (size_t)MQ * DINNER)             // 16384 x 1024 (tf32-rounded)
#define OFF_HOUT  (OFF_Y     + (size_t)MQ * DINNER)             // B*NC*1024*16
#define OFF_HIN   (OFF_HOUT  + (size_t)BQ * NCHUNK * DINNER * DSTATE)
#define OFF_SUMD  (OFF_HIN   + (size_t)BQ * NCHUNK * DINNER * DSTATE)
#define OFF_WINR  (OFF_SUMD  + (size_t)BQ * NCHUNK * DINNER)    // 2048 x 512 tf32-rounded W_in
#define OFF_WOUTR (OFF_WINR  + (size_t)2 * DINNER * DIMQ)       // 512 x 1024
#define OFF_WXPR  (OFF_WOUTR + (size_t)DIMQ * DINNER)           // 64 x 1024
#define SCRATCH_FLOATS (OFF_WXPR + (size_t)64 * DINNER)

__device__ __align__(128) float g_scratch[SCRATCH_FLOATS];

// ---------------- small device helpers ----------------
__device__ __forceinline__ float siluf(float x) { return x / (1.0f + __expf(-x)); }
__device__ __forceinline__ float softplusf(float x) {
    return (x > 20.0f) ? x : log1pf(__expf(x));
}
__device__ __forceinline__ void ld16(const float* p, float* v) {
    const float4* q = reinterpret_cast<const float4*>(p);
    float4 a = q[0], b = q[1], c = q[2], d = q[3];
    v[0]=a.x; v[1]=a.y; v[2]=a.z;  v[3]=a.w;
    v[4]=b.x; v[5]=b.y; v[6]=b.z;  v[7]=b.w;
    v[8]=c.x; v[9]=c.y; v[10]=c.z; v[11]=c.w;
    v[12]=d.x;v[13]=d.y;v[14]=d.z; v[15]=d.w;
}
__device__ __forceinline__ void st16(float* p, const float* v) {
    float4* q = reinterpret_cast<float4*>(p);
    q[0] = make_float4(v[0],  v[1],  v[2],  v[3]);
    q[1] = make_float4(v[4],  v[5],  v[6],  v[7]);
    q[2] = make_float4(v[8],  v[9],  v[10], v[11]);
    q[3] = make_float4(v[12], v[13], v[14], v[15]);
}

__device__ __forceinline__ uint32_t f2tf32(float x) {
    uint32_t u;
    asm("cvt.rna.tf32.f32 %0, %1;" : "=r"(u) : "f"(x));
    return u;
}
__device__ __forceinline__ void mma_tf32(float* c, const uint32_t* a, const uint32_t* b) {
    asm volatile(
        "mma.sync.aligned.m16n8k8.row.col.f32.tf32.tf32.f32 "
        "{%0,%1,%2,%3}, {%4,%5,%6,%7}, {%8,%9}, {%0,%1,%2,%3};"
        : "+f"(c[0]), "+f"(c[1]), "+f"(c[2]), "+f"(c[3])
        : "r"(a[0]), "r"(a[1]), "r"(a[2]), "r"(a[3]), "r"(b[0]), "r"(b[1]));
}
#define CP16(dst, src) \
    asm volatile("cp.async.ca.shared.global [%0], [%1], 16;\n" :: "r"(dst), "l"(src))

// ---------------- round a weight matrix to tf32 (once per launch) ----------------
__global__ void round_tf32_kernel(const float* __restrict__ src, size_t dstoff, int n)
{
    int i = blockIdx.x * 256 + threadIdx.x;
    if (i < n) g_scratch[dstoff + i] = __uint_as_float(f2tf32(src[i]));
}

// ---------------- LayerNorm: x (B,DIM,L) -> xn (B*L, DIM), tf32-rounded ----------------
// 32 l-positions per block -> full 128B coalesced line reads.
__global__ void ln_kernel(const float* __restrict__ x,
                          const float* __restrict__ w,
                          const float* __restrict__ bvec)
{
    extern __shared__ float tl[];            // [DIMQ][33]
    __shared__ float ssum[8][32], ssq[8][32];
    __shared__ float smu[32], sri[32];

    const int row0 = blockIdx.x * 32;
    const int b  = row0 / LQ;
    const int l0 = row0 % LQ;
    const int lj = threadIdx.x & 31;
    const int dg = threadIdx.x >> 5;         // 8 d-groups

    float sum = 0.0f, sq = 0.0f;
    const float* xb = x + (size_t)b * DIMQ * LQ + l0 + lj;
    for (int d = dg; d < DIMQ; d += 8) {
        float v = xb[(size_t)d * LQ];
        tl[d * 33 + lj] = v;
        sum += v;
        sq  += v * v;
    }
    ssum[dg][lj] = sum;
    ssq[dg][lj]  = sq;
    __syncthreads();

    if (threadIdx.x < 32) {
        float s = 0.0f, q = 0.0f;
        #pragma unroll
        for (int g = 0; g < 8; ++g) { s += ssum[g][threadIdx.x]; q += ssq[g][threadIdx.x]; }
        float mu  = s * (1.0f / DIMQ);
        float var = q * (1.0f / DIMQ) - mu * mu;
        smu[threadIdx.x] = mu;
        sri[threadIdx.x] = rsqrtf(var + 1e-5f);
    }
    __syncthreads();

    float* xn = g_scratch + OFF_XN;
    for (int idx = threadIdx.x; idx < DIMQ * 32; idx += 256) {
        int d  = idx & (DIMQ - 1);
        int ll = idx >> 9;
        float v = (tl[d * 33 + ll] - smu[ll]) * sri[ll] * w[d] + bvec[d];
        xn[(size_t)(row0 + ll) * DIMQ + d] = __uint_as_float(f2tf32(v));
    }
}

// ---------------- tf32 tensor-core GEMM: C[m][n] = sum_k A[m][k]*W[n][k] ----------------
// BK = 32 fixed. cp.async ring with NSTG stages (2 or 3).
// EPI 0: store to scratch; EPI 2: atomicAdd (split-K); EPI 3: n = (b,l), write outp[b][m][l].
// CVTA 1: convert A fragments on the fly; 0: A pre-rounded, reinterpret.
template<int BM, int BN, int WM, int WN, int EPI, int CVTA, int NSTG>
__global__ void __launch_bounds__((BM/WM)*(BN/WN)*32, 2)
mma_gemm(size_t aoff, size_t woff, size_t coff, float* __restrict__ outp,
         int lda, int ldw, int ldc, int kslice)
{
    constexpr int NWARP = (BM / WM) * (BN / WN);
    constexpr int NT    = NWARP * 32;
    constexpr int MI    = WM / 16;
    constexpr int NI    = WN / 8;
    constexpr int LDS_  = 36;
    constexpr int STAGE = (BM + BN) * LDS_;
    constexpr int APF   = BM * 8 / NT;
    constexpr int BPF   = BN * 8 / NT;

    extern __shared__ float sm[];

    const float* A = g_scratch + aoff;
    const float* W = g_scratch + woff;
    float*       C = g_scratch + coff;

    const int tid  = threadIdx.x;
    const int warp = tid >> 5, lane = tid & 31;
    const int wn   = (warp % (BN / WN)) * WN;
    const int wm   = (warp / (BN / WN)) * WM;
    const size_t m0 = (size_t)blockIdx.y * BM;
    const int    n0 = blockIdx.x * BN;
    const int kbase = blockIdx.z * kslice;
    const int niter = kslice / 32;

    float acc[MI][NI][4];
    #pragma unroll
    for (int i = 0; i < MI; ++i)
        #pragma unroll
        for (int j = 0; j < NI; ++j)
            #pragma unroll
            for (int q = 0; q < 4; ++q) acc[i][j][q] = 0.0f;

    auto issue = [&](int it, int stage) {
        const int k0 = kbase + it * 32;
        float* As = sm + stage * STAGE;
        float* Bs = As + BM * LDS_;
        #pragma unroll
        for (int p = 0; p < APF; ++p) {
            int idx = tid + p * NT;
            int row = idx >> 3, c4 = idx & 7;
            uint32_t dst = (uint32_t)__cvta_generic_to_shared(&As[row * LDS_ + c4 * 4]);
            const float* src = &A[(m0 + row) * (size_t)lda + k0 + c4 * 4];
            CP16(dst, src);
        }
        #pragma unroll
        for (int p = 0; p < BPF; ++p) {
            int idx = tid + p * NT;
            int row = idx >> 3, c4 = idx & 7;
            uint32_t dst = (uint32_t)__cvta_generic_to_shared(&Bs[row * LDS_ + c4 * 4]);
            const float* src = &W[(size_t)(n0 + row) * ldw + k0 + c4 * 4];
            CP16(dst, src);
        }
        asm volatile("cp.async.commit_group;\n" ::);
    };

    issue(0, 0);
    if (NSTG > 2 && niter > 1) issue(1, 1);
    const int r = lane >> 2, c = lane & 3;

    for (int it = 0; it < niter; ++it) {
        const int stage = it % NSTG;
        if (NSTG == 2) {
            if (it + 1 < niter) {
                issue(it + 1, (it + 1) % NSTG);
                asm volatile("cp.async.wait_group 1;\n" ::);
            } else {
                asm volatile("cp.async.wait_group 0;\n" ::);
            }
        } else {
            if (it + 2 < niter) {
                issue(it + 2, (it + 2) % NSTG);
                asm volatile("cp.async.wait_group 2;\n" ::);
            } else if (it + 1 < niter) {
                asm volatile("cp.async.wait_group 1;\n" ::);
            } else {
                asm volatile("cp.async.wait_group 0;\n" ::);
            }
        }
        __syncthreads();

        const float* As = sm + stage * STAGE + wm * LDS_;
        const float* Bs = sm + stage * STAGE + BM * LDS_ + wn * LDS_;

        #pragma unroll
        for (int s = 0; s < 4; ++s) {
            const int kk = s * 8;
            uint32_t af[MI][4];
            uint32_t bf[NI][2];
            #pragma unroll
            for (int mi = 0; mi < MI; ++mi) {
                const float* ap = As + (mi * 16 + r) * LDS_ + kk + c;
                if (CVTA) {
                    af[mi][0] = f2tf32(ap[0]);
                    af[mi][1] = f2tf32(ap[8 * LDS_]);
                    af[mi][2] = f2tf32(ap[4]);
                    af[mi][3] = f2tf32(ap[8 * LDS_ + 4]);
                } else {
                    af[mi][0] = __float_as_uint(ap[0]);
                    af[mi][1] = __float_as_uint(ap[8 * LDS_]);
                    af[mi][2] = __float_as_uint(ap[4]);
                    af[mi][3] = __float_as_uint(ap[8 * LDS_ + 4]);
                }
            }
            #pragma unroll
            for (int ni = 0; ni < NI; ++ni) {
                const float* bp = Bs + (ni * 8 + r) * LDS_ + kk + c;
                bf[ni][0] = __float_as_uint(bp[0]);
                bf[ni][1] = __float_as_uint(bp[4]);
            }
            #pragma unroll
            for (int mi = 0; mi < MI; ++mi)
                #pragma unroll
                for (int ni = 0; ni < NI; ++ni)
                    mma_tf32(acc[mi][ni], af[mi], bf[ni]);
        }
        __syncthreads();
    }

    const int c2 = (lane & 3) * 2;
    #pragma unroll
    for (int mi = 0; mi < MI; ++mi) {
        const size_t m = m0 + wm + mi * 16 + r;
        #pragma unroll
        for (int ni = 0; ni < NI; ++ni) {
            const int n = n0 + wn + ni * 8 + c2;
            if (EPI == 0) {
                *reinterpret_cast<float2*>(&C[m * (size_t)ldc + n]) =
                    make_float2(acc[mi][ni][0], acc[mi][ni][1]);
                *reinterpret_cast<float2*>(&C[(m + 8) * (size_t)ldc + n]) =
                    make_float2(acc[mi][ni][2], acc[mi][ni][3]);
            } else if (EPI == 3) {
                // n encodes (b,l); BN=128 tiles never straddle a batch boundary
                const int b = n >> 12;
                const int l = n & (LQ - 1);
                float* obase = outp + (size_t)b * DIMQ * LQ + l;
                *reinterpret_cast<float2*>(obase + m * (size_t)LQ) =
                    make_float2(acc[mi][ni][0], acc[mi][ni][1]);
                *reinterpret_cast<float2*>(obase + (m + 8) * (size_t)LQ) =
                    make_float2(acc[mi][ni][2], acc[mi][ni][3]);
            } else {
                atomicAdd(&C[m * (size_t)ldc + n],       acc[mi][ni][0]);
                atomicAdd(&C[m * (size_t)ldc + n + 1],   acc[mi][ni][1]);
                atomicAdd(&C[(m + 8) * (size_t)ldc + n],     acc[mi][ni][2]);
                atomicAdd(&C[(m + 8) * (size_t)ldc + n + 1], acc[mi][ni][3]);
            }
        }
    }
}

// ---------------- FFMA SGEMM (delta projection, K=32, fp32 kept for accuracy) ------
template<int BM, int BN, int BK, int TM, int TN, int EPI>
__global__ void __launch_bounds__((BM/TM)*(BN/TN), 2)
sgemm_tn(size_t aoff, const float* __restrict__ W,
         const float* __restrict__ bias, size_t coff,
         int K, int lda, int ldw, int ldc)
{
    constexpr int NT = (BM / TM) * (BN / TN);
    constexpr int KQ = BK / 4;
    __shared__ float As[BK][BM + 4];
    __shared__ float Bs[BK][BN + 4];

    const float* A = g_scratch + aoff;
    float*       C = g_scratch + coff;

    const int tid = threadIdx.x;
    const int tx  = tid % (BN / TN);
    const int ty  = tid / (BN / TN);
    const size_t m0 = (size_t)blockIdx.y * BM;
    const int    n0 = blockIdx.x * BN;

    float acc[TM][TN];
    #pragma unroll
    for (int i = 0; i < TM; ++i)
        #pragma unroll
        for (int j = 0; j < TN; ++j) acc[i][j] = 0.0f;

    for (int k0 = 0; k0 < K; k0 += BK) {
        for (int f = tid; f < BM * KQ; f += NT) {
            int m = f / KQ, kq = f % KQ;
            const float4 v = *reinterpret_cast<const float4*>(
                &A[(m0 + m) * lda + k0 + kq * 4]);
            As[kq*4 + 0][m] = v.x; As[kq*4 + 1][m] = v.y;
            As[kq*4 + 2][m] = v.z; As[kq*4 + 3][m] = v.w;
        }
        for (int f = tid; f < BN * KQ; f += NT) {
            int n = f / KQ, kq = f % KQ;
            const float4 v = *reinterpret_cast<const float4*>(
                &W[(size_t)(n0 + n) * ldw + k0 + kq * 4]);
            Bs[kq*4 + 0][n] = v.x; Bs[kq*4 + 1][n] = v.y;
            Bs[kq*4 + 2][n] = v.z; Bs[kq*4 + 3][n] = v.w;
        }
        __syncthreads();

        #pragma unroll
        for (int k = 0; k < BK; ++k) {
            float a[TM], bb[TN];
            #pragma unroll
            for (int i = 0; i < TM; ++i) a[i]  = As[k][ty * TM + i];
            #pragma unroll
            for (int j = 0; j < TN; ++j) bb[j] = Bs[k][tx * TN + j];
            #pragma unroll
            for (int i = 0; i < TM; ++i)
                #pragma unroll
                for (int j = 0; j < TN; ++j) acc[i][j] += a[i] * bb[j];
        }
        __syncthreads();
    }

    #pragma unroll
    for (int i = 0; i < TM; ++i) {
        const size_t m = m0 + ty * TM + i;
        #pragma unroll
        for (int j = 0; j < TN; ++j) {
            const int n = n0 + tx * TN + j;
            float v = acc[i][j];
            if (EPI == 1) v = softplusf(v + bias[n]);
            C[m * ldc + n] = v;
        }
    }
}

// ---------------- zero helper ----------------
__global__ void zero_kernel(size_t off, size_t n)
{
    for (size_t i = (size_t)blockIdx.x * blockDim.x + threadIdx.x; i < n;
         i += (size_t)gridDim.x * blockDim.x)
        g_scratch[off + i] = 0.0f;
}

// ---------------- causal depthwise conv (K=4) + bias + SiLU, l-tiled ----------------
#define CTL 16
__global__ void conv_silu(const float* __restrict__ conv_w,
                          const float* __restrict__ conv_b)
{
    const int b  = blockIdx.y;
    const int l0 = blockIdx.x * CTL;
    const float* xz = g_scratch + OFF_XZ;
    float*       u  = g_scratch + OFF_U;

    #pragma unroll
    for (int q = 0; q < 4; ++q) {
        const int c = threadIdx.x + q * 256;
        const float4 wv = reinterpret_cast<const float4*>(conv_w)[c];
        const float bias = conv_b[c];
        const size_t base = ((size_t)b * LQ + l0) * (2 * DINNER) + c;

        float x0 = 0.0f, x1 = 0.0f, x2 = 0.0f;
        if (l0 > 0) {
            x0 = xz[base - 3 * (size_t)(2 * DINNER)];
            x1 = xz[base - 2 * (size_t)(2 * DINNER)];
            x2 = xz[base - 1 * (size_t)(2 * DINNER)];
        }
        #pragma unroll
        for (int t = 0; t < CTL; ++t) {
            float x3 = xz[base + (size_t)t * (2 * DINNER)];
            float acc = bias + wv.x * x0 + wv.y * x1 + wv.z * x2 + wv.w * x3;
            u[((size_t)b * LQ + l0 + t) * DINNER + c] = siluf(acc);
            x0 = x1; x1 = x2; x2 = x3;
        }
    }
}

// ---------------- structured-A check (scalar, no persistent array) ----------------
__device__ __forceinline__ bool a_structured(const float* __restrict__ A_log, int d) {
    bool st = true;
    #pragma unroll
    for (int s = 0; s < DSTATE; ++s) {
        float a = __expf(A_log[d * DSTATE + s]);
        st = st && (fabsf(a - (float)(s + 1)) <= 1e-4f * (float)(s + 1));
    }
    return st;
}

// ---------------- selective scan: chunked (2-pass + stitch) ----------------
// Fast path exploits A_s = -(s+1): exp(delta*A_s) = p^(s+1), p = exp(-delta).
__global__ void scan_phase1(const float* __restrict__ A_log)
{
    const int d = blockIdx.x * 128 + threadIdx.x;
    const int c = blockIdx.y;
    const int b = blockIdx.z;

    const bool st = a_structured(A_log, d);

    float h[DSTATE];
    #pragma unroll
    for (int s = 0; s < DSTATE; ++s) h[s] = 0.0f;
    float sumd = 0.0f;

    const size_t rowbase = (size_t)b * LQ + (size_t)c * LCHUNK;
    const float* dl  = g_scratch + OFF_DELTA;
    const float* uu  = g_scratch + OFF_U;
    const float* dbl = g_scratch + OFF_DBL;

    if (st) {
        for (int t = 0; t < LCHUNK; ++t) {
            const size_t row = rowbase + t;
            const float delta = dl[row * DINNER + d];
            const float du    = delta * uu[row * DINNER + d];
            float Bv[DSTATE];
            ld16(dbl + row * 64 + DTRANK, Bv);
            sumd += delta;
            const float p  = __expf(-delta);
            const float p2 = p * p,  p4 = p2 * p2, p8 = p4 * p4;
            float pc = p;
            h[0] = pc * h[0] + du * Bv[0];            pc = p2;
            h[1] = pc * h[1] + du * Bv[1];            pc = p2 * p;
            h[2] = pc * h[2] + du * Bv[2];            pc = p4;
            h[3] = pc * h[3] + du * Bv[3];            pc = p4 * p;
            h[4] = pc * h[4] + du * Bv[4];            pc = p4 * p2;
            h[5] = pc * h[5] + du * Bv[5];            pc = p4 * p2 * p;
            h[6] = pc * h[6] + du * Bv[6];            pc = p8;
            h[7] = pc * h[7] + du * Bv[7];            pc = p8 * p;
            h[8] = pc * h[8] + du * Bv[8];            pc = p8 * p2;
            h[9] = pc * h[9] + du * Bv[9];            pc = p8 * p2 * p;
            h[10] = pc * h[10] + du * Bv[10];         pc = p8 * p4;
            h[11] = pc * h[11] + du * Bv[11];         pc = p8 * p4 * p;
            h[12] = pc * h[12] + du * Bv[12];         pc = p8 * p4 * p2;
            h[13] = pc * h[13] + du * Bv[13];         pc = p8 * p4 * p2 * p;
            h[14] = pc * h[14] + du * Bv[14];         pc = p8 * p8;
            h[15] = pc * h[15] + du * Bv[15];
        }
    } else {
        float Aa[DSTATE];
        #pragma unroll
        for (int s = 0; s < DSTATE; ++s) Aa[s] = -__expf(A_log[d * DSTATE + s]);
        for (int t = 0; t < LCHUNK; ++t) {
            const size_t row = rowbase + t;
            const float delta = dl[row * DINNER + d];
            const float du    = delta * uu[row * DINNER + d];
            float Bv[DSTATE];
            ld16(dbl + row * 64 + DTRANK, Bv);
            sumd += delta;
            #pragma unroll
            for (int s = 0; s < DSTATE; ++s)
                h[s] = __expf(delta * Aa[s]) * h[s] + du * Bv[s];
        }
    }

    const size_t o = ((size_t)(b * NCHUNK + c) * DINNER + d) * DSTATE;
    st16(g_scratch + OFF_HOUT + o, h);
    g_scratch[OFF_SUMD + (size_t)(b * NCHUNK + c) * DINNER + d] = sumd;
}

__global__ void scan_phase2(const float* __restrict__ A_log)
{
    const int d = blockIdx.x * 128 + threadIdx.x;
    const int b = blockIdx.y;

    float Aa[DSTATE];
    #pragma unroll
    for (int s = 0; s < DSTATE; ++s) Aa[s] = -__expf(A_log[d * DSTATE + s]);

    float h[DSTATE];
    #pragma unroll
    for (int s = 0; s < DSTATE; ++s) h[s] = 0.0f;

    for (int c = 0; c < NCHUNK; ++c) {
        const size_t o = ((size_t)(b * NCHUNK + c) * DINNER + d) * DSTATE;
        st16(g_scratch + OFF_HIN + o, h);
        const float sd = g_scratch[OFF_SUMD + (size_t)(b * NCHUNK + c) * DINNER + d];
        float ho[DSTATE];
        ld16(g_scratch + OFF_HOUT + o, ho);
        #pragma unroll
        for (int s = 0; s < DSTATE; ++s)
            h[s] = __expf(sd * Aa[s]) * h[s] + ho[s];
    }
}

__global__ void scan_phase3(const float* __restrict__ A_log,
                            const float* __restrict__ Dp)
{
    const int d = blockIdx.x * 128 + threadIdx.x;
    const int c = blockIdx.y;
    const int b = blockIdx.z;

    const bool st = a_structured(A_log, d);

    float h[DSTATE];
    ld16(g_scratch + OFF_HIN + ((size_t)(b * NCHUNK + c) * DINNER + d) * DSTATE, h);
    const float Dc = Dp[d];

    const size_t rowbase = (size_t)b * LQ + (size_t)c * LCHUNK;
    const float* dl  = g_scratch + OFF_DELTA;
    const float* uu  = g_scratch + OFF_U;
    const float* dbl = g_scratch + OFF_DBL;
    const float* xz  = g_scratch + OFF_XZ;
    float*       y   = g_scratch + OFF_Y;

    if (st) {
        for (int t = 0; t < LCHUNK; ++t) {
            const size_t row = rowbase + t;
            const float delta = dl[row * DINNER + d];
            const float u     = uu[row * DINNER + d];
            const float du    = delta * u;
            float Bv[DSTATE], Cv[DSTATE];
            ld16(dbl + row * 64 + DTRANK, Bv);
            ld16(dbl + row * 64 + DTRANK + DSTATE, Cv);
            const float p  = __expf(-delta);
            const float p2 = p * p,  p4 = p2 * p2, p8 = p4 * p4;
            float ys = 0.0f;
            float pc = p;
            h[0] = pc * h[0] + du * Bv[0];   ys += h[0] * Cv[0];    pc = p2;
            h[1] = pc * h[1] + du * Bv[1];   ys += h[1] * Cv[1];    pc = p2 * p;
            h[2] = pc * h[2] + du * Bv[2];   ys += h[2] * Cv[2];    pc = p4;
            h[3] = pc * h[3] + du * Bv[3];   ys += h[3] * Cv[3];    pc = p4 * p;
            h[4] = pc * h[4] + du * Bv[4];   ys += h[4] * Cv[4];    pc = p4 * p2;
            h[5] = pc * h[5] + du * Bv[5];   ys += h[5] * Cv[5];    pc = p4 * p2 * p;
            h[6] = pc * h[6] + du * Bv[6];   ys += h[6] * Cv[6];    pc = p8;
            h[7] = pc * h[7] + du * Bv[7];   ys += h[7] * Cv[7];    pc = p8 * p;
            h[8] = pc * h[8] + du * Bv[8];   ys += h[8] * Cv[8];    pc = p8 * p2;
            h[9] = pc * h[9] + du * Bv[9];   ys += h[9] * Cv[9];    pc = p8 * p2 * p;
            h[10] = pc * h[10] + du * Bv[10]; ys += h[10] * Cv[10]; pc = p8 * p4;
            h[11] = pc * h[11] + du * Bv[11]; ys += h[11] * Cv[11]; pc = p8 * p4 * p;
            h[12] = pc * h[12] + du * Bv[12]; ys += h[12] * Cv[12]; pc = p8 * p4 * p2;
            h[13] = pc * h[13] + du * Bv[13]; ys += h[13] * Cv[13]; pc = p8 * p4 * p2 * p;
            h[14] = pc * h[14] + du * Bv[14]; ys += h[14] * Cv[14]; pc = p8 * p8;
            h[15] = pc * h[15] + du * Bv[15]; ys += h[15] * Cv[15];
            const float z = xz[row * (2 * DINNER) + DINNER + d];
            y[row * DINNER + d] =
                __uint_as_float(f2tf32((ys + u * Dc) * siluf(z)));
        }
    } else {
        float Aa[DSTATE];
        #pragma unroll
        for (int s = 0; s < DSTATE; ++s) Aa[s] = -__expf(A_log[d * DSTATE + s]);
        for (int t = 0; t < LCHUNK; ++t) {
            const size_t row = rowbase + t;
            const float delta = dl[row * DINNER + d];
            const float u     = uu[row * DINNER + d];
            const float du    = delta * u;
            float Bv[DSTATE], Cv[DSTATE];
            ld16(dbl + row * 64 + DTRANK, Bv);
            ld16(dbl + row * 64 + DTRANK + DSTATE, Cv);
            float ys = 0.0f;
            #pragma unroll
            for (int s = 0; s < DSTATE; ++s) {
                h[s] = __expf(delta * Aa[s]) * h[s] + du * Bv[s];
                ys  += h[s] * Cv[s];
            }
            const float z = xz[row * (2 * DINNER) + DINNER + d];
            y[row * DINNER + d] =
                __uint_as_float(f2tf32((ys + u * Dc) * siluf(z)));
        }
    }
}

// ---------------- launch ----------------
extern "C" void kernel_launch(void* const* d_in, const int* in_sizes, int n_in,
                              void* d_out, int out_size)
{
    const float* x       = (const float*)d_in[0];
    const float* ln_w    = (const float*)d_in[1];
    const float* ln_b    = (const float*)d_in[2];
    const float* W_in    = (const float*)d_in[3];
    const float* conv_w  = (const float*)d_in[4];
    const float* conv_b  = (const float*)d_in[5];
    const float* W_xproj = (const float*)d_in[6];
    const float* W_dt    = (const float*)d_in[7];
    const float* b_dt    = (const float*)d_in[8];
    const float* A_log   = (const float*)d_in[9];
    const float* Dp      = (const float*)d_in[10];
    const float* W_out   = (const float*)d_in[11];
    float* out = (float*)d_out;

    const int SM_BIG3 = 3 * (128 + 128) * 36 * 4;  // 110592 B (3-stage)
    const int SM_XPJ  = 2 * (128 + 64)  * 36 * 4;  // 55296 B
    const int SM_LN   = DIMQ * 33 * 4;             // 67584 B
    static bool attr_done = false;
    if (!attr_done) {
        cudaFuncSetAttribute(mma_gemm<128,128,64,64,0,0,3>,
                             cudaFuncAttributeMaxDynamicSharedMemorySize, SM_BIG3);
        cudaFuncSetAttribute(mma_gemm<128,128,64,64,3,0,3>,
                             cudaFuncAttributeMaxDynamicSharedMemorySize, SM_BIG3);
        cudaFuncSetAttribute(mma_gemm<128,64,32,32,2,1,2>,
                             cudaFuncAttributeMaxDynamicSharedMemorySize, SM_XPJ);
        cudaFuncSetAttribute(ln_kernel,
                             cudaFuncAttributeMaxDynamicSharedMemorySize, SM_LN);
        attr_done = true;
    }

    // 0. round weights to tf32 once
    round_tf32_kernel<<<(2 * DINNER * DIMQ + 255) / 256, 256>>>(W_in,    OFF_WINR,  2 * DINNER * DIMQ);
    round_tf32_kernel<<<(DIMQ * DINNER + 255) / 256, 256>>>(W_out,   OFF_WOUTR, DIMQ * DINNER);
    round_tf32_kernel<<<(64 * DINNER + 255) / 256, 256>>>(W_xproj, OFF_WXPR,  64 * DINNER);

    // 1. LayerNorm (transposed read, 32-wide coalesced tiles), output tf32-rounded
    ln_kernel<<<MQ / 32, 256, SM_LN>>>(x, ln_w, ln_b);

    // 2. xz = xn @ W_in^T   (16384 x 2048, K=512)  [tf32 mma, 3-stage pipeline]
    mma_gemm<128,128,64,64,0,0,3><<<dim3((2 * DINNER) / 128, MQ / 128, 1), 128, SM_BIG3>>>(
        OFF_XN, OFF_WINR, OFF_XZ, nullptr, DIMQ, DIMQ, 2 * DINNER, DIMQ);

    // 3. depthwise causal conv + SiLU -> u  (l-tiled shift-register)
    conv_silu<<<dim3(LQ / CTL, BQ), 256>>>(conv_w, conv_b);

    // 4. dbl = u @ W_xproj^T  (16384 x 64, K=1024)  [tf32, split-K=4, atomic]
    zero_kernel<<<1024, 256>>>(OFF_DBL, (size_t)MQ * 64);
    mma_gemm<128,64,32,32,2,1,2><<<dim3(1, MQ / 128, 4), 256, SM_XPJ>>>(
        OFF_U, OFF_WXPR, OFF_DBL, nullptr, DINNER, DINNER, 64, DINNER / 4);

    // 5. delta = softplus(dt @ W_dt^T + b_dt)  (16384 x 1024, K=32, lda=64) [fp32, 8x8 tiles]
    sgemm_tn<128, 128, 8, 8, 8, 1><<<dim3(DINNER / 128, MQ / 128), 256>>>(
        OFF_DBL, W_dt, b_dt, OFF_DELTA, DTRANK, 64, DTRANK, DINNER);

    // 6-8. chunked selective scan + fused gating (power-tree fast path)
    scan_phase1<<<dim3(DINNER / 128, NCHUNK, BQ), 128>>>(A_log);
    scan_phase2<<<dim3(DINNER / 128, BQ), 128>>>(A_log);
    scan_phase3<<<dim3(DINNER / 128, NCHUNK, BQ), 128>>>(A_log, Dp);

    // 9. out[b][d][l] = sum_k W_out[d][k] * y[(b,l)][k]
    //    (M=512 d-rows, N=16384 (b,l) cols, K=1024) — direct transposed store
    mma_gemm<128,128,64,64,3,0,3><<<dim3(MQ / 128, DIMQ / 128, 1), 128, SM_BIG3>>>(
        OFF_WOUTR, OFF_Y, 0, out, DINNER, DINNER, 0, DINNER);
}

// round 14
// speedup vs baseline: 1.1382x; 1.1382x over previous
#include <cuda_runtime.h>
#include <cstddef>
#include <cstdint>

// ---------------- problem constants ----------------
#define BQ     4
#define DIMQ   512
#define LQ     4096
#define DSTATE 16
#define DINNER 1024
#define DTRANK 32
#define MQ     (BQ * LQ)            // 16384 rows (b,l)
#define NCHUNK 32
#define LCHUNK (LQ / NCHUNK)        // 128

// ---------------- scratch layout (floats) ----------------
#define OFF_XN    ((size_t)0)                                   // 16384 x 512 (tf32-rounded)
#define OFF_XZ    (OFF_XN    + (size_t)MQ * DIMQ)               // 16384 x 2048
#define OFF_U     (OFF_XZ    + (size_t)MQ * 2 * DINNER)         // 16384 x 1024
#define OFF_DBL   (OFF_U     + (size_t)MQ * DINNER)             // 16384 x 64
#define OFF_DELTA (OFF_DBL   + (size_t)MQ * 64)                 // 16384 x 1024
#define OFF_Y     (OFF_DELTA + (size_t)MQ * DINNER)             // 16384 x 1024 (tf32-rounded)
#define OFF_HOUT  (OFF_Y     + (size_t)MQ * DINNER)             // B*NC*1024*16
#define OFF_HIN   (OFF_HOUT  + (size_t)BQ * NCHUNK * DINNER * DSTATE)
#define OFF_SUMD  (OFF_HIN   + (size_t)BQ * NCHUNK * DINNER * DSTATE)
#define OFF_WINR  (OFF_SUMD  + (size_t)BQ * NCHUNK * DINNER)    // 2048 x 512 tf32-rounded W_in
#define OFF_WOUTR (OFF_WINR  + (size_t)2 * DINNER * DIMQ)       // 512 x 1024
#define OFF_WXPR  (OFF_WOUTR + (size_t)DIMQ * DINNER)           // 64 x 1024
#define SCRATCH_FLOATS (OFF_WXPR + (size_t)64 * DINNER)

__device__ __align__(128) float g_scratch[SCRATCH_FLOATS];

// ---------------- small device helpers ----------------
__device__ __forceinline__ float siluf(float x) { return x / (1.0f + __expf(-x)); }
__device__ __forceinline__ float softplusf(float x) {
    return (x > 20.0f) ? x : log1pf(__expf(x));
}
__device__ __forceinline__ void ld16(const float* p, float* v) {
    const float4* q = reinterpret_cast<const float4*>(p);
    float4 a = q[0], b = q[1], c = q[2], d = q[3];
    v[0]=a.x; v[1]=a.y; v[2]=a.z;  v[3]=a.w;
    v[4]=b.x; v[5]=b.y; v[6]=b.z;  v[7]=b.w;
    v[8]=c.x; v[9]=c.y; v[10]=c.z; v[11]=c.w;
    v[12]=d.x;v[13]=d.y;v[14]=d.z; v[15]=d.w;
}
__device__ __forceinline__ void st16(float* p, const float* v) {
    float4* q = reinterpret_cast<float4*>(p);
    q[0] = make_float4(v[0],  v[1],  v[2],  v[3]);
    q[1] = make_float4(v[4],  v[5],  v[6],  v[7]);
    q[2] = make_float4(v[8],  v[9],  v[10], v[11]);
    q[3] = make_float4(v[12], v[13], v[14], v[15]);
}

__device__ __forceinline__ uint32_t f2tf32(float x) {
    uint32_t u;
    asm("cvt.rna.tf32.f32 %0, %1;" : "=r"(u) : "f"(x));
    return u;
}
__device__ __forceinline__ void mma_tf32(float* c, const uint32_t* a, const uint32_t* b) {
    asm volatile(
        "mma.sync.aligned.m16n8k8.row.col.f32.tf32.tf32.f32 "
        "{%0,%1,%2,%3}, {%4,%5,%6,%7}, {%8,%9}, {%0,%1,%2,%3};"
        : "+f"(c[0]), "+f"(c[1]), "+f"(c[2]), "+f"(c[3])
        : "r"(a[0]), "r"(a[1]), "r"(a[2]), "r"(a[3]), "r"(b[0]), "r"(b[1]));
}
#define CP16(dst, src) \
    asm volatile("cp.async.ca.shared.global [%0], [%1], 16;\n" :: "r"(dst), "l"(src))

// ---------------- round a weight matrix to tf32 (once per launch) ----------------
__global__ void round_tf32_kernel(const float* __restrict__ src, size_t dstoff, int n)
{
    int i = blockIdx.x * 256 + threadIdx.x;
    if (i < n) g_scratch[dstoff + i] = __uint_as_float(f2tf32(src[i]));
}

// ---------------- LayerNorm: x (B,DIM,L) -> xn (B*L, DIM), tf32-rounded ----------------
__global__ void ln_kernel(const float* __restrict__ x,
                          const float* __restrict__ w,
                          const float* __restrict__ bvec)
{
    __shared__ float tile[DIMQ][17];
    __shared__ float ssum[8][16], ssq[8][16];
    __shared__ float smu[16], sri[16];

    const int row0 = blockIdx.x * 16;
    const int b  = row0 / LQ;
    const int l0 = row0 % LQ;
    const int lj = threadIdx.x & 15;
    const int dg = threadIdx.x >> 4;

    float sum = 0.0f, sq = 0.0f;
    const float* xb = x + (size_t)b * DIMQ * LQ + l0 + lj;
    for (int d = dg; d < DIMQ; d += 8) {
        float v = xb[(size_t)d * LQ];
        tile[d][lj] = v;
        sum += v;
        sq  += v * v;
    }
    ssum[dg][lj] = sum;
    ssq[dg][lj]  = sq;
    __syncthreads();

    if (threadIdx.x < 16) {
        float s = 0.0f, q = 0.0f;
        #pragma unroll
        for (int g = 0; g < 8; ++g) { s += ssum[g][threadIdx.x]; q += ssq[g][threadIdx.x]; }
        float mu  = s * (1.0f / DIMQ);
        float var = q * (1.0f / DIMQ) - mu * mu;
        smu[threadIdx.x] = mu;
        sri[threadIdx.x] = rsqrtf(var + 1e-5f);
    }
    __syncthreads();

    float* xn = g_scratch + OFF_XN;
    for (int idx = threadIdx.x; idx < DIMQ * 16; idx += 128) {
        int d  = idx & (DIMQ - 1);
        int ll = idx >> 9;
        float v = (tile[d][ll] - smu[ll]) * sri[ll] * w[d] + bvec[d];
        xn[(size_t)(row0 + ll) * DIMQ + d] = __uint_as_float(f2tf32(v));
    }
}

// ---------------- tf32 tensor-core GEMM: C[m][n] = sum_k A[m][k]*W[n][k] ----------------
// BK = 32 fixed. cp.async double-buffered.
// EPI 0: store to scratch; EPI 3: n = (b,l), write outp[b][m][l].
// CVTA 1: convert A fragments on the fly; 0: A pre-rounded, reinterpret.
template<int BM, int BN, int WM, int WN, int EPI, int CVTA>
__global__ void __launch_bounds__((BM/WM)*(BN/WN)*32, 2)
mma_gemm(size_t aoff, size_t woff, size_t coff, float* __restrict__ outp,
         int lda, int ldw, int ldc, int kslice)
{
    constexpr int NWARP = (BM / WM) * (BN / WN);
    constexpr int NT    = NWARP * 32;
    constexpr int MI    = WM / 16;
    constexpr int NI    = WN / 8;
    constexpr int LDS_  = 36;
    constexpr int STAGE = (BM + BN) * LDS_;
    constexpr int APF   = BM * 8 / NT;
    constexpr int BPF   = BN * 8 / NT;

    extern __shared__ float sm[];

    const float* A = g_scratch + aoff;
    const float* W = g_scratch + woff;
    float*       C = g_scratch + coff;

    const int tid  = threadIdx.x;
    const int warp = tid >> 5, lane = tid & 31;
    const int wn   = (warp % (BN / WN)) * WN;
    const int wm   = (warp / (BN / WN)) * WM;
    const size_t m0 = (size_t)blockIdx.y * BM;
    const int    n0 = blockIdx.x * BN;
    const int kbase = blockIdx.z * kslice;
    const int niter = kslice / 32;

    float acc[MI][NI][4];
    #pragma unroll
    for (int i = 0; i < MI; ++i)
        #pragma unroll
        for (int j = 0; j < NI; ++j)
            #pragma unroll
            for (int q = 0; q < 4; ++q) acc[i][j][q] = 0.0f;

    auto issue = [&](int it, int stage) {
        const int k0 = kbase + it * 32;
        float* As = sm + stage * STAGE;
        float* Bs = As + BM * LDS_;
        #pragma unroll
        for (int p = 0; p < APF; ++p) {
            int idx = tid + p * NT;
            int row = idx >> 3, c4 = idx & 7;
            uint32_t dst = (uint32_t)__cvta_generic_to_shared(&As[row * LDS_ + c4 * 4]);
            const float* src = &A[(m0 + row) * (size_t)lda + k0 + c4 * 4];
            CP16(dst, src);
        }
        #pragma unroll
        for (int p = 0; p < BPF; ++p) {
            int idx = tid + p * NT;
            int row = idx >> 3, c4 = idx & 7;
            uint32_t dst = (uint32_t)__cvta_generic_to_shared(&Bs[row * LDS_ + c4 * 4]);
            const float* src = &W[(size_t)(n0 + row) * ldw + k0 + c4 * 4];
            CP16(dst, src);
        }
        asm volatile("cp.async.commit_group;\n" ::);
    };

    issue(0, 0);
    const int r = lane >> 2, c = lane & 3;

    for (int it = 0; it < niter; ++it) {
        const int stage = it & 1;
        if (it + 1 < niter) {
            issue(it + 1, stage ^ 1);
            asm volatile("cp.async.wait_group 1;\n" ::);
        } else {
            asm volatile("cp.async.wait_group 0;\n" ::);
        }
        __syncthreads();

        const float* As = sm + stage * STAGE + wm * LDS_;
        const float* Bs = sm + stage * STAGE + BM * LDS_ + wn * LDS_;

        #pragma unroll
        for (int s = 0; s < 4; ++s) {
            const int kk = s * 8;
            uint32_t af[MI][4];
            uint32_t bf[NI][2];
            #pragma unroll
            for (int mi = 0; mi < MI; ++mi) {
                const float* ap = As + (mi * 16 + r) * LDS_ + kk + c;
                if (CVTA) {
                    af[mi][0] = f2tf32(ap[0]);
                    af[mi][1] = f2tf32(ap[8 * LDS_]);
                    af[mi][2] = f2tf32(ap[4]);
                    af[mi][3] = f2tf32(ap[8 * LDS_ + 4]);
                } else {
                    af[mi][0] = __float_as_uint(ap[0]);
                    af[mi][1] = __float_as_uint(ap[8 * LDS_]);
                    af[mi][2] = __float_as_uint(ap[4]);
                    af[mi][3] = __float_as_uint(ap[8 * LDS_ + 4]);
                }
            }
            #pragma unroll
            for (int ni = 0; ni < NI; ++ni) {
                const float* bp = Bs + (ni * 8 + r) * LDS_ + kk + c;
                bf[ni][0] = __float_as_uint(bp[0]);
                bf[ni][1] = __float_as_uint(bp[4]);
            }
            #pragma unroll
            for (int mi = 0; mi < MI; ++mi)
                #pragma unroll
                for (int ni = 0; ni < NI; ++ni)
                    mma_tf32(acc[mi][ni], af[mi], bf[ni]);
        }
        __syncthreads();
    }

    const int c2 = (lane & 3) * 2;
    #pragma unroll
    for (int mi = 0; mi < MI; ++mi) {
        const size_t m = m0 + wm + mi * 16 + r;
        #pragma unroll
        for (int ni = 0; ni < NI; ++ni) {
            const int n = n0 + wn + ni * 8 + c2;
            if (EPI == 0) {
                *reinterpret_cast<float2*>(&C[m * (size_t)ldc + n]) =
                    make_float2(acc[mi][ni][0], acc[mi][ni][1]);
                *reinterpret_cast<float2*>(&C[(m + 8) * (size_t)ldc + n]) =
                    make_float2(acc[mi][ni][2], acc[mi][ni][3]);
            } else if (EPI == 3) {
                // n encodes (b,l); BN=128 tiles never straddle a batch boundary
                const int b = n >> 12;
                const int l = n & (LQ - 1);
                float* obase = outp + (size_t)b * DIMQ * LQ + l;
                *reinterpret_cast<float2*>(obase + m * (size_t)LQ) =
                    make_float2(acc[mi][ni][0], acc[mi][ni][1]);
                *reinterpret_cast<float2*>(obase + (m + 8) * (size_t)LQ) =
                    make_float2(acc[mi][ni][2], acc[mi][ni][3]);
            }
        }
    }
}

// ---------------- FFMA SGEMM (tiny delta projection, K=32) ----------------
template<int BM, int BN, int BK, int TM, int TN, int EPI>
__global__ void __launch_bounds__((BM/TM)*(BN/TN), 2)
sgemm_tn(size_t aoff, const float* __restrict__ W,
         const float* __restrict__ bias, size_t coff,
         int K, int lda, int ldw, int ldc)
{
    constexpr int NT = (BM / TM) * (BN / TN);
    constexpr int KQ = BK / 4;
    __shared__ float As[BK][BM + 4];
    __shared__ float Bs[BK][BN + 4];

    const float* A = g_scratch + aoff;
    float*       C = g_scratch + coff;

    const int tid = threadIdx.x;
    const int tx  = tid % (BN / TN);
    const int ty  = tid / (BN / TN);
    const size_t m0 = (size_t)blockIdx.y * BM;
    const int    n0 = blockIdx.x * BN;

    float acc[TM][TN];
    #pragma unroll
    for (int i = 0; i < TM; ++i)
        #pragma unroll
        for (int j = 0; j < TN; ++j) acc[i][j] = 0.0f;

    for (int k0 = 0; k0 < K; k0 += BK) {
        for (int f = tid; f < BM * KQ; f += NT) {
            int m = f / KQ, kq = f % KQ;
            const float4 v = *reinterpret_cast<const float4*>(
                &A[(m0 + m) * lda + k0 + kq * 4]);
            As[kq*4 + 0][m] = v.x; As[kq*4 + 1][m] = v.y;
            As[kq*4 + 2][m] = v.z; As[kq*4 + 3][m] = v.w;
        }
        for (int f = tid; f < BN * KQ; f += NT) {
            int n = f / KQ, kq = f % KQ;
            const float4 v = *reinterpret_cast<const float4*>(
                &W[(size_t)(n0 + n) * ldw + k0 + kq * 4]);
            Bs[kq*4 + 0][n] = v.x; Bs[kq*4 + 1][n] = v.y;
            Bs[kq*4 + 2][n] = v.z; Bs[kq*4 + 3][n] = v.w;
        }
        __syncthreads();

        #pragma unroll
        for (int k = 0; k < BK; ++k) {
            float a[TM], bb[TN];
            #pragma unroll
            for (int i = 0; i < TM; ++i) a[i]  = As[k][ty * TM + i];
            #pragma unroll
            for (int j = 0; j < TN; ++j) bb[j] = Bs[k][tx * TN + j];
            #pragma unroll
            for (int i = 0; i < TM; ++i)
                #pragma unroll
                for (int j = 0; j < TN; ++j) acc[i][j] += a[i] * bb[j];
        }
        __syncthreads();
    }

    #pragma unroll
    for (int i = 0; i < TM; ++i) {
        const size_t m = m0 + ty * TM + i;
        #pragma unroll
        for (int j = 0; j < TN; ++j) {
            const int n = n0 + tx * TN + j;
            float v = acc[i][j];
            if (EPI == 1) v = softplusf(v + bias[n]);
            C[m * ldc + n] = v;
        }
    }
}

// ---------------- causal depthwise conv (K=4) + bias + SiLU, l-tiled ----------------
#define CTL 16
__global__ void conv_silu(const float* __restrict__ conv_w,
                          const float* __restrict__ conv_b)
{
    const int b  = blockIdx.y;
    const int l0 = blockIdx.x * CTL;
    const float* xz = g_scratch + OFF_XZ;
    float*       u  = g_scratch + OFF_U;

    #pragma unroll
    for (int q = 0; q < 4; ++q) {
        const int c = threadIdx.x + q * 256;
        const float4 wv = reinterpret_cast<const float4*>(conv_w)[c];
        const float bias = conv_b[c];
        const size_t base = ((size_t)b * LQ + l0) * (2 * DINNER) + c;

        float x0 = 0.0f, x1 = 0.0f, x2 = 0.0f;
        if (l0 > 0) {
            x0 = xz[base - 3 * (size_t)(2 * DINNER)];
            x1 = xz[base - 2 * (size_t)(2 * DINNER)];
            x2 = xz[base - 1 * (size_t)(2 * DINNER)];
        }
        #pragma unroll
        for (int t = 0; t < CTL; ++t) {
            float x3 = xz[base + (size_t)t * (2 * DINNER)];
            float acc = bias + wv.x * x0 + wv.y * x1 + wv.z * x2 + wv.w * x3;
            u[((size_t)b * LQ + l0 + t) * DINNER + c] = siluf(acc);
            x0 = x1; x1 = x2; x2 = x3;
        }
    }
}

// ---------------- structured-A check (scalar, no persistent array) ----------------
__device__ __forceinline__ bool a_structured(const float* __restrict__ A_log, int d) {
    bool st = true;
    #pragma unroll
    for (int s = 0; s < DSTATE; ++s) {
        float a = __expf(A_log[d * DSTATE + s]);
        st = st && (fabsf(a - (float)(s + 1)) <= 1e-4f * (float)(s + 1));
    }
    return st;
}

// ---------------- selective scan: chunked (2-pass + stitch) ----------------
// Fast path exploits A_s = -(s+1): exp(delta*A_s) = p^(s+1), p = exp(-delta).
__global__ void scan_phase1(const float* __restrict__ A_log)
{
    const int d = blockIdx.x * 128 + threadIdx.x;
    const int c = blockIdx.y;
    const int b = blockIdx.z;

    const bool st = a_structured(A_log, d);

    float h[DSTATE];
    #pragma unroll
    for (int s = 0; s < DSTATE; ++s) h[s] = 0.0f;
    float sumd = 0.0f;

    const size_t rowbase = (size_t)b * LQ + (size_t)c * LCHUNK;
    const float* dl  = g_scratch + OFF_DELTA;
    const float* uu  = g_scratch + OFF_U;
    const float* dbl = g_scratch + OFF_DBL;

    if (st) {
        for (int t = 0; t < LCHUNK; ++t) {
            const size_t row = rowbase + t;
            const float delta = dl[row * DINNER + d];
            const float du    = delta * uu[row * DINNER + d];
            float Bv[DSTATE];
            ld16(dbl + row * 64 + DTRANK, Bv);
            sumd += delta;
            const float p  = __expf(-delta);
            const float p2 = p * p,  p4 = p2 * p2, p8 = p4 * p4;
            float pc = p;
            h[0] = pc * h[0] + du * Bv[0];            pc = p2;
            h[1] = pc * h[1] + du * Bv[1];            pc = p2 * p;
            h[2] = pc * h[2] + du * Bv[2];            pc = p4;
            h[3] = pc * h[3] + du * Bv[3];            pc = p4 * p;
            h[4] = pc * h[4] + du * Bv[4];            pc = p4 * p2;
            h[5] = pc * h[5] + du * Bv[5];            pc = p4 * p2 * p;
            h[6] = pc * h[6] + du * Bv[6];            pc = p8;
            h[7] = pc * h[7] + du * Bv[7];            pc = p8 * p;
            h[8] = pc * h[8] + du * Bv[8];            pc = p8 * p2;
            h[9] = pc * h[9] + du * Bv[9];            pc = p8 * p2 * p;
            h[10] = pc * h[10] + du * Bv[10];         pc = p8 * p4;
            h[11] = pc * h[11] + du * Bv[11];         pc = p8 * p4 * p;
            h[12] = pc * h[12] + du * Bv[12];         pc = p8 * p4 * p2;
            h[13] = pc * h[13] + du * Bv[13];         pc = p8 * p4 * p2 * p;
            h[14] = pc * h[14] + du * Bv[14];         pc = p8 * p8;
            h[15] = pc * h[15] + du * Bv[15];
        }
    } else {
        float Aa[DSTATE];
        #pragma unroll
        for (int s = 0; s < DSTATE; ++s) Aa[s] = -__expf(A_log[d * DSTATE + s]);
        for (int t = 0; t < LCHUNK; ++t) {
            const size_t row = rowbase + t;
            const float delta = dl[row * DINNER + d];
            const float du    = delta * uu[row * DINNER + d];
            float Bv[DSTATE];
            ld16(dbl + row * 64 + DTRANK, Bv);
            sumd += delta;
            #pragma unroll
            for (int s = 0; s < DSTATE; ++s)
                h[s] = __expf(delta * Aa[s]) * h[s] + du * Bv[s];
        }
    }

    const size_t o = ((size_t)(b * NCHUNK + c) * DINNER + d) * DSTATE;
    st16(g_scratch + OFF_HOUT + o, h);
    g_scratch[OFF_SUMD + (size_t)(b * NCHUNK + c) * DINNER + d] = sumd;
}

__global__ void scan_phase2(const float* __restrict__ A_log)
{
    const int d = blockIdx.x * 128 + threadIdx.x;
    const int b = blockIdx.y;

    float Aa[DSTATE];
    #pragma unroll
    for (int s = 0; s < DSTATE; ++s) Aa[s] = -__expf(A_log[d * DSTATE + s]);

    float h[DSTATE];
    #pragma unroll
    for (int s = 0; s < DSTATE; ++s) h[s] = 0.0f;

    for (int c = 0; c < NCHUNK; ++c) {
        const size_t o = ((size_t)(b * NCHUNK + c) * DINNER + d) * DSTATE;
        st16(g_scratch + OFF_HIN + o, h);
        const float sd = g_scratch[OFF_SUMD + (size_t)(b * NCHUNK + c) * DINNER + d];
        float ho[DSTATE];
        ld16(g_scratch + OFF_HOUT + o, ho);
        #pragma unroll
        for (int s = 0; s < DSTATE; ++s)
            h[s] = __expf(sd * Aa[s]) * h[s] + ho[s];
    }
}

__global__ void scan_phase3(const float* __restrict__ A_log,
                            const float* __restrict__ Dp)
{
    const int d = blockIdx.x * 128 + threadIdx.x;
    const int c = blockIdx.y;
    const int b = blockIdx.z;

    const bool st = a_structured(A_log, d);

    float h[DSTATE];
    ld16(g_scratch + OFF_HIN + ((size_t)(b * NCHUNK + c) * DINNER + d) * DSTATE, h);
    const float Dc = Dp[d];

    const size_t rowbase = (size_t)b * LQ + (size_t)c * LCHUNK;
    const float* dl  = g_scratch + OFF_DELTA;
    const float* uu  = g_scratch + OFF_U;
    const float* dbl = g_scratch + OFF_DBL;
    const float* xz  = g_scratch + OFF_XZ;
    float*       y   = g_scratch + OFF_Y;

    if (st) {
        for (int t = 0; t < LCHUNK; ++t) {
            const size_t row = rowbase + t;
            const float delta = dl[row * DINNER + d];
            const float u     = uu[row * DINNER + d];
            const float du    = delta * u;
            float Bv[DSTATE], Cv[DSTATE];
            ld16(dbl + row * 64 + DTRANK, Bv);
            ld16(dbl + row * 64 + DTRANK + DSTATE, Cv);
            const float p  = __expf(-delta);
            const float p2 = p * p,  p4 = p2 * p2, p8 = p4 * p4;
            float ys = 0.0f;
            float pc = p;
            h[0] = pc * h[0] + du * Bv[0];   ys += h[0] * Cv[0];    pc = p2;
            h[1] = pc * h[1] + du * Bv[1];   ys += h[1] * Cv[1];    pc = p2 * p;
            h[2] = pc * h[2] + du * Bv[2];   ys += h[2] * Cv[2];    pc = p4;
            h[3] = pc * h[3] + du * Bv[3];   ys += h[3] * Cv[3];    pc = p4 * p;
            h[4] = pc * h[4] + du * Bv[4];   ys += h[4] * Cv[4];    pc = p4 * p2;
            h[5] = pc * h[5] + du * Bv[5];   ys += h[5] * Cv[5];    pc = p4 * p2 * p;
            h[6] = pc * h[6] + du * Bv[6];   ys += h[6] * Cv[6];    pc = p8;
            h[7] = pc * h[7] + du * Bv[7];   ys += h[7] * Cv[7];    pc = p8 * p;
            h[8] = pc * h[8] + du * Bv[8];   ys += h[8] * Cv[8];    pc = p8 * p2;
            h[9] = pc * h[9] + du * Bv[9];   ys += h[9] * Cv[9];    pc = p8 * p2 * p;
            h[10] = pc * h[10] + du * Bv[10]; ys += h[10] * Cv[10]; pc = p8 * p4;
            h[11] = pc * h[11] + du * Bv[11]; ys += h[11] * Cv[11]; pc = p8 * p4 * p;
            h[12] = pc * h[12] + du * Bv[12]; ys += h[12] * Cv[12]; pc = p8 * p4 * p2;
            h[13] = pc * h[13] + du * Bv[13]; ys += h[13] * Cv[13]; pc = p8 * p4 * p2 * p;
            h[14] = pc * h[14] + du * Bv[14]; ys += h[14] * Cv[14]; pc = p8 * p8;
            h[15] = pc * h[15] + du * Bv[15]; ys += h[15] * Cv[15];
            const float z = xz[row * (2 * DINNER) + DINNER + d];
            y[row * DINNER + d] =
                __uint_as_float(f2tf32((ys + u * Dc) * siluf(z)));
        }
    } else {
        float Aa[DSTATE];
        #pragma unroll
        for (int s = 0; s < DSTATE; ++s) Aa[s] = -__expf(A_log[d * DSTATE + s]);
        for (int t = 0; t < LCHUNK; ++t) {
            const size_t row = rowbase + t;
            const float delta = dl[row * DINNER + d];
            const float u     = uu[row * DINNER + d];
            const float du    = delta * u;
            float Bv[DSTATE], Cv[DSTATE];
            ld16(dbl + row * 64 + DTRANK, Bv);
            ld16(dbl + row * 64 + DTRANK + DSTATE, Cv);
            float ys = 0.0f;
            #pragma unroll
            for (int s = 0; s < DSTATE; ++s) {
                h[s] = __expf(delta * Aa[s]) * h[s] + du * Bv[s];
                ys  += h[s] * Cv[s];
            }
            const float z = xz[row * (2 * DINNER) + DINNER + d];
            y[row * DINNER + d] =
                __uint_as_float(f2tf32((ys + u * Dc) * siluf(z)));
        }
    }
}

// ---------------- launch ----------------
extern "C" void kernel_launch(void* const* d_in, const int* in_sizes, int n_in,
                              void* d_out, int out_size)
{
    const float* x       = (const float*)d_in[0];
    const float* ln_w    = (const float*)d_in[1];
    const float* ln_b    = (const float*)d_in[2];
    const float* W_in    = (const float*)d_in[3];
    const float* conv_w  = (const float*)d_in[4];
    const float* conv_b  = (const float*)d_in[5];
    const float* W_xproj = (const float*)d_in[6];
    const float* W_dt    = (const float*)d_in[7];
    const float* b_dt    = (const float*)d_in[8];
    const float* A_log   = (const float*)d_in[9];
    const float* Dp      = (const float*)d_in[10];
    const float* W_out   = (const float*)d_in[11];
    float* out = (float*)d_out;

    const int SM_BIG = 2 * (128 + 128) * 36 * 4;   // 73728 B (2-stage, 2 CTAs/SM)
    const int SM_XPJ = 2 * (64 + 64)   * 36 * 4;   // 36864 B
    static bool attr_done = false;
    if (!attr_done) {
        cudaFuncSetAttribute(mma_gemm<128,128,64,64,0,0>,
                             cudaFuncAttributeMaxDynamicSharedMemorySize, SM_BIG);
        cudaFuncSetAttribute(mma_gemm<128,128,64,64,3,0>,
                             cudaFuncAttributeMaxDynamicSharedMemorySize, SM_BIG);
        cudaFuncSetAttribute(mma_gemm<64,64,32,32,0,1>,
                             cudaFuncAttributeMaxDynamicSharedMemorySize, SM_XPJ);
        attr_done = true;
    }

    // 0. round weights to tf32 once
    round_tf32_kernel<<<(2 * DINNER * DIMQ + 255) / 256, 256>>>(W_in,    OFF_WINR,  2 * DINNER * DIMQ);
    round_tf32_kernel<<<(DIMQ * DINNER + 255) / 256, 256>>>(W_out,   OFF_WOUTR, DIMQ * DINNER);
    round_tf32_kernel<<<(64 * DINNER + 255) / 256, 256>>>(W_xproj, OFF_WXPR,  64 * DINNER);

    // 1. LayerNorm (transposed read), output tf32-rounded  [R11 version]
    ln_kernel<<<MQ / 16, 128>>>(x, ln_w, ln_b);

    // 2. xz = xn @ W_in^T   (16384 x 2048, K=512)  [tf32 mma, WM=WN=64, 2-stage]
    mma_gemm<128,128,64,64,0,0><<<dim3((2 * DINNER) / 128, MQ / 128, 1), 128, SM_BIG>>>(
        OFF_XN, OFF_WINR, OFF_XZ, nullptr, DIMQ, DIMQ, 2 * DINNER, DIMQ);

    // 3. depthwise causal conv + SiLU -> u  (l-tiled shift-register)
    conv_silu<<<dim3(LQ / CTL, BQ), 256>>>(conv_w, conv_b);

    // 4. dbl = u @ W_xproj^T  (16384 x 64, K=1024)
    //    [tf32, NO split-K: 64x64 tiles, 256 CTAs, direct store — no zero, no atomics]
    mma_gemm<64,64,32,32,0,1><<<dim3(1, MQ / 64, 1), 128, SM_XPJ>>>(
        OFF_U, OFF_WXPR, OFF_DBL, nullptr, DINNER, DINNER, 64, DINNER);

    // 5. delta = softplus(dt @ W_dt^T + b_dt)  (16384 x 1024, K=32, lda=64)  [R11 version]
    sgemm_tn<128, 64, 8, 8, 4, 1><<<dim3(DINNER / 64, MQ / 128), 256>>>(
        OFF_DBL, W_dt, b_dt, OFF_DELTA, DTRANK, 64, DTRANK, DINNER);

    // 6-8. chunked selective scan + fused gating (power-tree fast path)
    scan_phase1<<<dim3(DINNER / 128, NCHUNK, BQ), 128>>>(A_log);
    scan_phase2<<<dim3(DINNER / 128, BQ), 128>>>(A_log);
    scan_phase3<<<dim3(DINNER / 128, NCHUNK, BQ), 128>>>(A_log, Dp);

    // 9. out[b][d][l] = sum_k W_out[d][k] * y[(b,l)][k]
    //    (M=512 d-rows, N=16384 (b,l) cols, K=1024) — direct transposed store
    mma_gemm<128,128,64,64,3,0><<<dim3(MQ / 128, DIMQ / 128, 1), 128, SM_BIG>>>(
        OFF_WOUTR, OFF_Y, 0, out, DINNER, DINNER, 0, DINNER);
}